// round 2
// baseline (speedup 1.0000x reference)
#include <cuda_runtime.h>
#include <cuda_bf16.h>
#include <math_constants.h>

// Problem shape (fixed by the dataset)
#define BATCH 2
#define SEQ   2048
#define DMODEL 1024
#define NHEAD 16
#define HDIM  64
#define MROWS (BATCH*SEQ)          // 4096

// ---------------------------------------------------------------------------
// Scratch (allocation-free rule: __device__ globals, referenced directly from
// kernels — no cudaGetSymbolAddress in the capture path)
// ---------------------------------------------------------------------------
__device__ float g_qkv[(size_t)MROWS * 3 * DMODEL];   // [4096][3072]
__device__ float g_att[(size_t)MROWS * DMODEL];       // [4096][1024]

// ---------------------------------------------------------------------------
// Classic 128x128x8 register-blocked SGEMM: C = A@B + bias
// A: [M,K] row-major, B: [K,N] row-major, bias: [N]
// 256 threads, 8x8 per thread. M,N % 128 == 0, K % 8 == 0.
// Mode selects where A comes from / where C goes (globals vs params).
//   mode 0: C = param A  @ B -> g_qkv
//   mode 1: C = g_att    @ B -> param C
// ---------------------------------------------------------------------------
template<int MODE>
__global__ __launch_bounds__(256) void sgemm128(
    const float* __restrict__ Ap, const float* __restrict__ B,
    const float* __restrict__ bias, float* __restrict__ Cp,
    int M, int N, int K)
{
    const float* A = (MODE == 0) ? Ap : (const float*)g_att;
    float*       C = (MODE == 0) ? (float*)g_qkv : Cp;

    __shared__ float As[8][128];   // transposed: As[k][m]
    __shared__ float Bs[8][128];   // Bs[k][n]

    const int tid = threadIdx.x;
    const int bm = blockIdx.y * 128;
    const int bn = blockIdx.x * 128;
    const int ty = tid >> 4;       // 0..15 -> rows ty*8..+7
    const int tx = tid & 15;       // 0..15 -> cols tx*8..+7

    const int arow = tid >> 1;          // 0..127
    const int acol = (tid & 1) * 4;     // 0 or 4
    const int brow = tid >> 5;          // 0..7
    const int bcol = (tid & 31) * 4;    // 0..124

    float acc[8][8];
#pragma unroll
    for (int i = 0; i < 8; i++)
#pragma unroll
        for (int j = 0; j < 8; j++) acc[i][j] = 0.f;

    const float* Aptr = A + (size_t)(bm + arow) * K + acol;
    const float* Bptr = B + (size_t)brow * N + bn + bcol;

    for (int k0 = 0; k0 < K; k0 += 8) {
        float4 a = *(const float4*)(Aptr + k0);
        As[acol + 0][arow] = a.x;
        As[acol + 1][arow] = a.y;
        As[acol + 2][arow] = a.z;
        As[acol + 3][arow] = a.w;
        *(float4*)&Bs[brow][bcol] = *(const float4*)(Bptr + (size_t)k0 * N);
        __syncthreads();

#pragma unroll
        for (int k = 0; k < 8; k++) {
            float ra[8], rb[8];
            *(float4*)(ra)     = *(const float4*)&As[k][ty * 8];
            *(float4*)(ra + 4) = *(const float4*)&As[k][ty * 8 + 4];
            *(float4*)(rb)     = *(const float4*)&Bs[k][tx * 8];
            *(float4*)(rb + 4) = *(const float4*)&Bs[k][tx * 8 + 4];
#pragma unroll
            for (int i = 0; i < 8; i++)
#pragma unroll
                for (int j = 0; j < 8; j++)
                    acc[i][j] = fmaf(ra[i], rb[j], acc[i][j]);
        }
        __syncthreads();
    }

    // Epilogue: + bias, vectorized stores
#pragma unroll
    for (int i = 0; i < 8; i++) {
        const int row = bm + ty * 8 + i;
        float* crow = C + (size_t)row * N + bn + tx * 8;
#pragma unroll
        for (int j = 0; j < 8; j += 4) {
            float4 o;
            o.x = acc[i][j + 0] + bias[bn + tx * 8 + j + 0];
            o.y = acc[i][j + 1] + bias[bn + tx * 8 + j + 1];
            o.z = acc[i][j + 2] + bias[bn + tx * 8 + j + 2];
            o.w = acc[i][j + 3] + bias[bn + tx * 8 + j + 3];
            *(float4*)(crow + j) = o;
        }
    }
}

// ---------------------------------------------------------------------------
// Flash attention, fp32 SIMT.
// Grid: (16 q-tiles, 32 batch*head). Block: 256 threads.
// Per block: 128 query rows, full head dim 64, loop over 32 key tiles of 64.
// Thread (ty=tid/16, tx=tid%16): owns rows ty*8+i (i<8), cols tx*4+j (j<4)
// for both the S tile (64 keys wide) and the O accumulator (64 dims wide).
// ---------------------------------------------------------------------------
#define QS_STRIDE 68      // 64 + 4 pad (keeps float4 smem accesses 16B aligned)
#define FLASH_SMEM_FLOATS (128*QS_STRIDE + 64*QS_STRIDE + 64*QS_STRIDE + 128*QS_STRIDE + 64)
#define FLASH_SMEM_BYTES  (FLASH_SMEM_FLOATS * 4)

__global__ __launch_bounds__(256) void flash_attn(
    const float* __restrict__ attn_bias)  // [2][2048]
{
    const float* qkv = (const float*)g_qkv;   // [4096][3072]
    float* att       = (float*)g_att;         // [4096][1024]

    extern __shared__ float smem[];
    float* Qs    = smem;                          // [128][68]
    float* Kst   = Qs  + 128 * QS_STRIDE;         // [64 d][68 keys]  (transposed)
    float* Vs    = Kst + 64 * QS_STRIDE;          // [64 key][68 d]
    float* Ps    = Vs  + 64 * QS_STRIDE;          // [128][68]
    float* biass = Ps  + 128 * QS_STRIDE;         // [64]

    const int tid = threadIdx.x;
    const int ty = tid >> 4;      // 0..15
    const int tx = tid & 15;      // 0..15
    const int qtile = blockIdx.x; // 0..15
    const int bh = blockIdx.y;    // 0..31
    const int b = bh >> 4;
    const int h = bh & 15;
    const int q0 = qtile * 128;

    const float scale = 0.125f;   // 1/sqrt(64)

    // ---- load Q tile once: rows q0..q0+127, cols h*64..+63 (part 0) ----
    {
        const float* qbase = qkv + ((size_t)(b * SEQ + q0)) * 3072 + h * HDIM;
#pragma unroll
        for (int rep = 0; rep < 8; rep++) {
            int idx = rep * 256 + tid;      // 0..2047
            int row = idx >> 4;
            int c4  = (idx & 15) * 4;
            float4 v = *(const float4*)(qbase + (size_t)row * 3072 + c4);
            *(float4*)&Qs[row * QS_STRIDE + c4] = v;
        }
    }

    float O[8][4];
    float mrow[8], lrow[8];
#pragma unroll
    for (int i = 0; i < 8; i++) {
        mrow[i] = -CUDART_INF_F;
        lrow[i] = 0.f;
#pragma unroll
        for (int j = 0; j < 4; j++) O[i][j] = 0.f;
    }

    for (int kt = 0; kt < SEQ / 64; kt++) {
        // ---- load K (transposed), V, bias for this tile ----
        const float* kbase = qkv + ((size_t)(b * SEQ + kt * 64)) * 3072 + DMODEL + h * HDIM;
        const float* vbase = kbase + DMODEL;   // part 2
#pragma unroll
        for (int rep = 0; rep < 4; rep++) {
            int idx = rep * 256 + tid;       // 0..1023
            int key = idx >> 4;
            int c4  = (idx & 15) * 4;
            float4 kv = *(const float4*)(kbase + (size_t)key * 3072 + c4);
            Kst[(c4 + 0) * QS_STRIDE + key] = kv.x;
            Kst[(c4 + 1) * QS_STRIDE + key] = kv.y;
            Kst[(c4 + 2) * QS_STRIDE + key] = kv.z;
            Kst[(c4 + 3) * QS_STRIDE + key] = kv.w;
            float4 vv = *(const float4*)(vbase + (size_t)key * 3072 + c4);
            *(float4*)&Vs[key * QS_STRIDE + c4] = vv;
        }
        if (tid < 16) {
            *(float4*)&biass[tid * 4] =
                *(const float4*)(attn_bias + (size_t)b * SEQ + kt * 64 + tid * 4);
        }
        __syncthreads();

        // ---- S = Q @ K^T  (128 x 64), per-thread 8x4 ----
        float sv[8][4];
#pragma unroll
        for (int i = 0; i < 8; i++)
#pragma unroll
            for (int j = 0; j < 4; j++) sv[i][j] = 0.f;

#pragma unroll 8
        for (int d = 0; d < 64; d++) {
            float rq[8];
#pragma unroll
            for (int i = 0; i < 8; i++) rq[i] = Qs[(ty * 8 + i) * QS_STRIDE + d];
            float4 rk = *(const float4*)&Kst[d * QS_STRIDE + tx * 4];
#pragma unroll
            for (int i = 0; i < 8; i++) {
                sv[i][0] = fmaf(rq[i], rk.x, sv[i][0]);
                sv[i][1] = fmaf(rq[i], rk.y, sv[i][1]);
                sv[i][2] = fmaf(rq[i], rk.z, sv[i][2]);
                sv[i][3] = fmaf(rq[i], rk.w, sv[i][3]);
            }
        }

        float bj[4];
#pragma unroll
        for (int j = 0; j < 4; j++) bj[j] = biass[tx * 4 + j];

        // ---- online softmax update ----
#pragma unroll
        for (int i = 0; i < 8; i++) {
#pragma unroll
            for (int j = 0; j < 4; j++) sv[i][j] = fmaf(sv[i][j], scale, bj[j]);

            float mt = fmaxf(fmaxf(sv[i][0], sv[i][1]), fmaxf(sv[i][2], sv[i][3]));
#pragma unroll
            for (int msk = 8; msk >= 1; msk >>= 1)
                mt = fmaxf(mt, __shfl_xor_sync(0xffffffffu, mt, msk));

            float mnew = fmaxf(mrow[i], mt);
            float alpha = __expf(mrow[i] - mnew);
            mrow[i] = mnew;

            float p0 = __expf(sv[i][0] - mnew);
            float p1 = __expf(sv[i][1] - mnew);
            float p2 = __expf(sv[i][2] - mnew);
            float p3 = __expf(sv[i][3] - mnew);
            *(float4*)&Ps[(ty * 8 + i) * QS_STRIDE + tx * 4] = make_float4(p0, p1, p2, p3);

            float rs = p0 + p1 + p2 + p3;
#pragma unroll
            for (int msk = 8; msk >= 1; msk >>= 1)
                rs += __shfl_xor_sync(0xffffffffu, rs, msk);

            lrow[i] = lrow[i] * alpha + rs;
#pragma unroll
            for (int j = 0; j < 4; j++) O[i][j] *= alpha;
        }
        __syncthreads();

        // ---- O += P @ V  (128 x 64), per-thread 8x4 ----
#pragma unroll 8
        for (int jk = 0; jk < 64; jk++) {
            float rp[8];
#pragma unroll
            for (int i = 0; i < 8; i++) rp[i] = Ps[(ty * 8 + i) * QS_STRIDE + jk];
            float4 rv = *(const float4*)&Vs[jk * QS_STRIDE + tx * 4];
#pragma unroll
            for (int i = 0; i < 8; i++) {
                O[i][0] = fmaf(rp[i], rv.x, O[i][0]);
                O[i][1] = fmaf(rp[i], rv.y, O[i][1]);
                O[i][2] = fmaf(rp[i], rv.z, O[i][2]);
                O[i][3] = fmaf(rp[i], rv.w, O[i][3]);
            }
        }
        __syncthreads();
    }

    // ---- epilogue: normalize and store to g_att ----
    float* obase = att + ((size_t)(b * SEQ + q0)) * DMODEL + h * HDIM + tx * 4;
#pragma unroll
    for (int i = 0; i < 8; i++) {
        float inv = 1.0f / lrow[i];
        float4 o = make_float4(O[i][0] * inv, O[i][1] * inv, O[i][2] * inv, O[i][3] * inv);
        *(float4*)(obase + (size_t)(ty * 8 + i) * DMODEL) = o;
    }
}

// ---------------------------------------------------------------------------
// Launch
// ---------------------------------------------------------------------------
extern "C" void kernel_launch(void* const* d_in, const int* in_sizes, int n_in,
                              void* d_out, int out_size)
{
    const float* x        = (const float*)d_in[0];
    const float* attnb    = (const float*)d_in[1];
    const float* w_qkv    = (const float*)d_in[2];
    const float* b_qkv    = (const float*)d_in[3];
    const float* w_proj   = (const float*)d_in[4];
    const float* b_proj   = (const float*)d_in[5];
    float* out = (float*)d_out;

    cudaFuncSetAttribute(flash_attn, cudaFuncAttributeMaxDynamicSharedMemorySize,
                         FLASH_SMEM_BYTES);

    // 1) qkv = x @ w_qkv + b_qkv    [4096,1024]@[1024,3072] -> g_qkv
    sgemm128<0><<<dim3(3 * DMODEL / 128, MROWS / 128), 256>>>(
        x, w_qkv, b_qkv, nullptr, MROWS, 3 * DMODEL, DMODEL);

    // 2) attention (flash, per (b,h,qtile)): g_qkv -> g_att
    flash_attn<<<dim3(SEQ / 128, BATCH * NHEAD), 256, FLASH_SMEM_BYTES>>>(attnb);

    // 3) out = g_att @ w_proj + b_proj   [4096,1024]@[1024,1024]
    sgemm128<1><<<dim3(DMODEL / 128, MROWS / 128), 256>>>(
        nullptr, w_proj, b_proj, out, MROWS, DMODEL, DMODEL);
}

// round 3
// speedup vs baseline: 2.5028x; 2.5028x over previous
#include <cuda_runtime.h>
#include <cuda_bf16.h>
#include <math_constants.h>
#include <cstdint>

// Problem shape (fixed by the dataset)
#define BATCH 2
#define SEQ   2048
#define DMODEL 1024
#define NHEAD 16
#define HDIM  64
#define MROWS (BATCH*SEQ)          // 4096

// ---------------------------------------------------------------------------
// Scratch (allocation-free rule: __device__ globals)
// ---------------------------------------------------------------------------
__device__ float g_qkv[(size_t)MROWS * 3 * DMODEL];   // [4096][3072]
__device__ float g_att[(size_t)MROWS * DMODEL];       // [4096][1024]

// ---------------------------------------------------------------------------
// tf32 helpers
// ---------------------------------------------------------------------------
__device__ __forceinline__ uint32_t f2tf(float x) {
    uint32_t u;
    asm("cvt.rna.tf32.f32 %0, %1;" : "=r"(u) : "f"(x));
    return u;
}

// D(16x8) += A(16x8) * B(8x8); A row-major frag, B col-major frag, fp32 accum.
__device__ __forceinline__ void mma8(float* c, const uint32_t* a, const uint32_t* b) {
    asm volatile(
        "mma.sync.aligned.m16n8k8.row.col.f32.tf32.tf32.f32 "
        "{%0,%1,%2,%3}, {%4,%5,%6,%7}, {%8,%9}, {%0,%1,%2,%3};\n"
        : "+f"(c[0]), "+f"(c[1]), "+f"(c[2]), "+f"(c[3])
        : "r"(a[0]), "r"(a[1]), "r"(a[2]), "r"(a[3]), "r"(b[0]), "r"(b[1]));
}

// ---------------------------------------------------------------------------
// tf32 tensor-core GEMM: C = A@B + bias
// A: [M,K] row-major fp32, B: [K,N] row-major fp32, bias: [N]
// Block tile 128x128, BK=16. 256 threads = 8 warps as 4(m) x 2(n);
// warp tile 32x64 = 2 m-tiles x 8 n-tiles of m16n8k8.
//   MODE 0: C = Ap @ B -> g_qkv       MODE 1: C = g_att @ B -> Cp
// ---------------------------------------------------------------------------
#define ASTRIDE 20     // [m][k] tile, k=16 + pad 4  -> bank = (4g+q)%32, conflict-free
#define BSTRIDE 136    // [k][n] tile, n=128 + pad 8 -> bank = (8q+g)%32, conflict-free

template<int MODE>
__global__ __launch_bounds__(256) void tgemm(
    const float* __restrict__ Ap, const float* __restrict__ B,
    const float* __restrict__ bias, float* __restrict__ Cp,
    int M, int N, int K)
{
    const float* A = (MODE == 0) ? Ap : (const float*)g_att;
    float*       C = (MODE == 0) ? (float*)g_qkv : Cp;

    __shared__ uint32_t As[128][ASTRIDE];   // tf32 bits, [m][k0..15]
    __shared__ uint32_t Bs[16][BSTRIDE];    // tf32 bits, [k][n0..127]

    const int tid  = threadIdx.x;
    const int lane = tid & 31;
    const int wid  = tid >> 5;
    const int g    = lane >> 2;     // 0..7
    const int q    = lane & 3;      // 0..3

    const int bm = blockIdx.y * 128;
    const int bn = blockIdx.x * 128;

    const int wm0 = (wid >> 1) * 32;   // warp m-offset (0,32,64,96)
    const int wn0 = (wid & 1) * 64;    // warp n-offset (0,64)

    // global load assignments
    const int arow = tid >> 1;             // 0..127
    const int acol = (tid & 1) * 8;        // 0 or 8
    const int brow = tid >> 4;             // 0..15
    const int bcol = (tid & 15) * 8;       // 0..120

    const float* Aptr = A + (size_t)(bm + arow) * K + acol;
    const float* Bptr = B + (size_t)brow * N + bn + bcol;

    float acc[2][8][4];
#pragma unroll
    for (int mt = 0; mt < 2; mt++)
#pragma unroll
        for (int j = 0; j < 8; j++)
#pragma unroll
            for (int r = 0; r < 4; r++) acc[mt][j][r] = 0.f;

    for (int k0 = 0; k0 < K; k0 += 16) {
        // ---- load A tile (128x16) ----
        {
            float4 v0 = *(const float4*)(Aptr + k0);
            float4 v1 = *(const float4*)(Aptr + k0 + 4);
            uint4 u0 = make_uint4(f2tf(v0.x), f2tf(v0.y), f2tf(v0.z), f2tf(v0.w));
            uint4 u1 = make_uint4(f2tf(v1.x), f2tf(v1.y), f2tf(v1.z), f2tf(v1.w));
            *(uint4*)&As[arow][acol]     = u0;
            *(uint4*)&As[arow][acol + 4] = u1;
        }
        // ---- load B tile (16x128) ----
        {
            float4 v0 = *(const float4*)(Bptr + (size_t)k0 * N);
            float4 v1 = *(const float4*)(Bptr + (size_t)k0 * N + 4);
            uint4 u0 = make_uint4(f2tf(v0.x), f2tf(v0.y), f2tf(v0.z), f2tf(v0.w));
            uint4 u1 = make_uint4(f2tf(v1.x), f2tf(v1.y), f2tf(v1.z), f2tf(v1.w));
            *(uint4*)&Bs[brow][bcol]     = u0;
            *(uint4*)&Bs[brow][bcol + 4] = u1;
        }
        __syncthreads();

#pragma unroll
        for (int ks = 0; ks < 16; ks += 8) {
            uint32_t af[2][4];
#pragma unroll
            for (int mt = 0; mt < 2; mt++) {
                const int m = wm0 + mt * 16 + g;
                af[mt][0] = As[m][ks + q];
                af[mt][1] = As[m + 8][ks + q];
                af[mt][2] = As[m][ks + q + 4];
                af[mt][3] = As[m + 8][ks + q + 4];
            }
            uint32_t bf[8][2];
#pragma unroll
            for (int j = 0; j < 8; j++) {
                bf[j][0] = Bs[ks + q][wn0 + j * 8 + g];
                bf[j][1] = Bs[ks + q + 4][wn0 + j * 8 + g];
            }
#pragma unroll
            for (int mt = 0; mt < 2; mt++)
#pragma unroll
                for (int j = 0; j < 8; j++)
                    mma8(acc[mt][j], af[mt], bf[j]);
        }
        __syncthreads();
    }

    // ---- epilogue: + bias ----
#pragma unroll
    for (int mt = 0; mt < 2; mt++) {
        const int row0 = bm + wm0 + mt * 16 + g;
#pragma unroll
        for (int j = 0; j < 8; j++) {
            const int col = bn + wn0 + j * 8 + 2 * q;
            const float b0 = bias[col], b1 = bias[col + 1];
            *(float2*)&C[(size_t)row0 * N + col] =
                make_float2(acc[mt][j][0] + b0, acc[mt][j][1] + b1);
            *(float2*)&C[(size_t)(row0 + 8) * N + col] =
                make_float2(acc[mt][j][2] + b0, acc[mt][j][3] + b1);
        }
    }
}

// ---------------------------------------------------------------------------
// Flash attention, tf32 tensor cores.
// Grid: (16 q-tiles, 32 batch*head). Block: 256 threads = 8 warps.
// Warp w owns q-rows w*16..w*16+15. Key tiles of 64, hd = 64.
// S-mma: A=Q(16xK8 over d), B=K^T; PV-mma: A=P(16xK8 over keys), B=V.
// ---------------------------------------------------------------------------
#define QSTR 68        // Qs/Ps stride: bank = (4g+q)%32 conflict-free for A frags
#define KSTR 68        // Ks stride: B-frag bank = (4g+q)%32 conflict-free
#define VSTR 72        // Vs stride: B-frag bank = (8q+g)%32 conflict-free

#define SM_Q  0
#define SM_K  (SM_Q + 128 * QSTR)
#define SM_V  (SM_K + 64 * KSTR)
#define SM_P  (SM_V + 64 * VSTR)
#define SM_BIAS (SM_P + 128 * QSTR)
#define FLASH_SMEM_WORDS (SM_BIAS + 64)
#define FLASH_SMEM_BYTES (FLASH_SMEM_WORDS * 4)

__global__ __launch_bounds__(256) void flash_tf32(
    const float* __restrict__ attn_bias)   // [2][2048]
{
    const float* qkv = (const float*)g_qkv;
    float* att       = (float*)g_att;

    extern __shared__ uint32_t smw[];
    uint32_t* Qs = smw + SM_Q;     // [128][QSTR]
    uint32_t* Ks = smw + SM_K;     // [64][KSTR]   row=key, col=d
    uint32_t* Vs = smw + SM_V;     // [64][VSTR]   row=key, col=d
    uint32_t* Ps = smw + SM_P;     // [128][QSTR]
    float* biass = (float*)(smw + SM_BIAS);

    const int tid  = threadIdx.x;
    const int lane = tid & 31;
    const int wid  = tid >> 5;     // 0..7
    const int g    = lane >> 2;
    const int q    = lane & 3;

    const int qtile = blockIdx.x;  // 0..15
    const int bh    = blockIdx.y;  // 0..31
    const int b = bh >> 4;
    const int h = bh & 15;
    const int q0 = qtile * 128;

    const int m = wid * 16 + g;    // this thread's base q-row in tile (rows m, m+8)

    // ---- load Q tile (128 x 64) as tf32 ----
    {
        const float* qbase = qkv + ((size_t)(b * SEQ + q0)) * 3072 + h * HDIM;
#pragma unroll
        for (int rep = 0; rep < 8; rep++) {
            int idx = rep * 256 + tid;       // 0..2047 (x4 floats)
            int row = idx >> 4;
            int c4  = (idx & 15) * 4;
            float4 v = *(const float4*)(qbase + (size_t)row * 3072 + c4);
            *(uint4*)&Qs[row * QSTR + c4] =
                make_uint4(f2tf(v.x), f2tf(v.y), f2tf(v.z), f2tf(v.w));
        }
    }

    float o[8][4];
    float mr0 = -CUDART_INF_F, mr1 = -CUDART_INF_F;
    float l0 = 0.f, l1 = 0.f;
#pragma unroll
    for (int j = 0; j < 8; j++)
#pragma unroll
        for (int r = 0; r < 4; r++) o[j][r] = 0.f;

    for (int kt = 0; kt < SEQ / 64; kt++) {
        __syncthreads();   // protect Ks/Vs from previous iteration's readers
        // ---- load K, V (64 x 64 each) ----
        {
            const float* kbase = qkv + ((size_t)(b * SEQ + kt * 64)) * 3072 + DMODEL + h * HDIM;
            const float* vbase = kbase + DMODEL;
#pragma unroll
            for (int rep = 0; rep < 4; rep++) {
                int idx = rep * 256 + tid;   // 0..1023
                int key = idx >> 4;
                int c4  = (idx & 15) * 4;
                float4 kv = *(const float4*)(kbase + (size_t)key * 3072 + c4);
                *(uint4*)&Ks[key * KSTR + c4] =
                    make_uint4(f2tf(kv.x), f2tf(kv.y), f2tf(kv.z), f2tf(kv.w));
                float4 vv = *(const float4*)(vbase + (size_t)key * 3072 + c4);
                *(uint4*)&Vs[key * VSTR + c4] =
                    make_uint4(f2tf(vv.x), f2tf(vv.y), f2tf(vv.z), f2tf(vv.w));
            }
            if (tid < 16)
                *(float4*)&biass[tid * 4] =
                    *(const float4*)(attn_bias + (size_t)b * SEQ + kt * 64 + tid * 4);
        }
        __syncthreads();

        // ---- S = Q @ K^T : warp computes 16 x 64 ----
        float s[8][4];
#pragma unroll
        for (int j = 0; j < 8; j++)
#pragma unroll
            for (int r = 0; r < 4; r++) s[j][r] = 0.f;

#pragma unroll
        for (int ks = 0; ks < 64; ks += 8) {
            uint32_t af[4];
            af[0] = Qs[m * QSTR + ks + q];
            af[1] = Qs[(m + 8) * QSTR + ks + q];
            af[2] = Qs[m * QSTR + ks + q + 4];
            af[3] = Qs[(m + 8) * QSTR + ks + q + 4];
#pragma unroll
            for (int j = 0; j < 8; j++) {
                uint32_t bf[2];
                bf[0] = Ks[(j * 8 + g) * KSTR + ks + q];
                bf[1] = Ks[(j * 8 + g) * KSTR + ks + q + 4];
                mma8(s[j], af, bf);
            }
        }

        // ---- scale + bias, online softmax ----
        float mt0 = -CUDART_INF_F, mt1 = -CUDART_INF_F;
#pragma unroll
        for (int j = 0; j < 8; j++) {
            const int col = j * 8 + 2 * q;
            const float b0 = biass[col], b1 = biass[col + 1];
            s[j][0] = fmaf(s[j][0], 0.125f, b0);
            s[j][1] = fmaf(s[j][1], 0.125f, b1);
            s[j][2] = fmaf(s[j][2], 0.125f, b0);
            s[j][3] = fmaf(s[j][3], 0.125f, b1);
            mt0 = fmaxf(mt0, fmaxf(s[j][0], s[j][1]));
            mt1 = fmaxf(mt1, fmaxf(s[j][2], s[j][3]));
        }
        mt0 = fmaxf(mt0, __shfl_xor_sync(0xffffffffu, mt0, 1));
        mt0 = fmaxf(mt0, __shfl_xor_sync(0xffffffffu, mt0, 2));
        mt1 = fmaxf(mt1, __shfl_xor_sync(0xffffffffu, mt1, 1));
        mt1 = fmaxf(mt1, __shfl_xor_sync(0xffffffffu, mt1, 2));

        const float mn0 = fmaxf(mr0, mt0);
        const float mn1 = fmaxf(mr1, mt1);
        const float a0 = __expf(mr0 - mn0);
        const float a1 = __expf(mr1 - mn1);
        mr0 = mn0; mr1 = mn1;

        float rs0 = 0.f, rs1 = 0.f;
#pragma unroll
        for (int j = 0; j < 8; j++) {
            float p0 = __expf(s[j][0] - mn0);
            float p1 = __expf(s[j][1] - mn0);
            float p2 = __expf(s[j][2] - mn1);
            float p3 = __expf(s[j][3] - mn1);
            rs0 += p0 + p1;
            rs1 += p2 + p3;
            const int col = j * 8 + 2 * q;
            *(uint2*)&Ps[m * QSTR + col]       = make_uint2(f2tf(p0), f2tf(p1));
            *(uint2*)&Ps[(m + 8) * QSTR + col] = make_uint2(f2tf(p2), f2tf(p3));
        }
        rs0 += __shfl_xor_sync(0xffffffffu, rs0, 1);
        rs0 += __shfl_xor_sync(0xffffffffu, rs0, 2);
        rs1 += __shfl_xor_sync(0xffffffffu, rs1, 1);
        rs1 += __shfl_xor_sync(0xffffffffu, rs1, 2);
        l0 = l0 * a0 + rs0;
        l1 = l1 * a1 + rs1;

#pragma unroll
        for (int j = 0; j < 8; j++) {
            o[j][0] *= a0; o[j][1] *= a0;
            o[j][2] *= a1; o[j][3] *= a1;
        }
        __syncwarp();   // Ps is warp-private; order stores before frag loads

        // ---- O += P @ V : warp computes 16 x 64 ----
#pragma unroll
        for (int ks = 0; ks < 64; ks += 8) {
            uint32_t af[4];
            af[0] = Ps[m * QSTR + ks + q];
            af[1] = Ps[(m + 8) * QSTR + ks + q];
            af[2] = Ps[m * QSTR + ks + q + 4];
            af[3] = Ps[(m + 8) * QSTR + ks + q + 4];
#pragma unroll
            for (int j = 0; j < 8; j++) {
                uint32_t bf[2];
                bf[0] = Vs[(ks + q) * VSTR + j * 8 + g];
                bf[1] = Vs[(ks + q + 4) * VSTR + j * 8 + g];
                mma8(o[j], af, bf);
            }
        }
        __syncwarp();
    }

    // ---- epilogue: normalize, store ----
    const float inv0 = 1.0f / l0;
    const float inv1 = 1.0f / l1;
    const size_t row0 = (size_t)(b * SEQ + q0 + m);
#pragma unroll
    for (int j = 0; j < 8; j++) {
        const int col = h * HDIM + j * 8 + 2 * q;
        *(float2*)&att[row0 * DMODEL + col] =
            make_float2(o[j][0] * inv0, o[j][1] * inv0);
        *(float2*)&att[(row0 + 8) * DMODEL + col] =
            make_float2(o[j][2] * inv1, o[j][3] * inv1);
    }
}

// ---------------------------------------------------------------------------
// Launch
// ---------------------------------------------------------------------------
extern "C" void kernel_launch(void* const* d_in, const int* in_sizes, int n_in,
                              void* d_out, int out_size)
{
    const float* x      = (const float*)d_in[0];
    const float* attnb  = (const float*)d_in[1];
    const float* w_qkv  = (const float*)d_in[2];
    const float* b_qkv  = (const float*)d_in[3];
    const float* w_proj = (const float*)d_in[4];
    const float* b_proj = (const float*)d_in[5];
    float* out = (float*)d_out;

    cudaFuncSetAttribute(flash_tf32, cudaFuncAttributeMaxDynamicSharedMemorySize,
                         FLASH_SMEM_BYTES);

    // 1) qkv = x @ w_qkv + b_qkv    [4096,1024]@[1024,3072] -> g_qkv
    tgemm<0><<<dim3(3 * DMODEL / 128, MROWS / 128), 256>>>(
        x, w_qkv, b_qkv, nullptr, MROWS, 3 * DMODEL, DMODEL);

    // 2) attention: g_qkv -> g_att
    flash_tf32<<<dim3(SEQ / 128, BATCH * NHEAD), 256, FLASH_SMEM_BYTES>>>(attnb);

    // 3) out = g_att @ w_proj + b_proj   [4096,1024]@[1024,1024]
    tgemm<1><<<dim3(DMODEL / 128, MROWS / 128), 256>>>(
        nullptr, w_proj, b_proj, out, MROWS, DMODEL, DMODEL);
}

// round 5
// speedup vs baseline: 2.8975x; 1.1577x over previous
#include <cuda_runtime.h>
#include <cuda_bf16.h>
#include <math_constants.h>
#include <cstdint>

// Problem shape (fixed by the dataset)
#define BATCH 2
#define SEQ   2048
#define DMODEL 1024
#define NHEAD 16
#define HDIM  64
#define MROWS (BATCH*SEQ)          // 4096

// ---------------------------------------------------------------------------
// Single 64 MiB heap (same total as the known-passing R3 config), aliased:
//   [0, 12M words)        : qkv tf32 [4096][3072]  (GEMM1 out, flash in)
//                           ... later reused for w_projT [1024][1024] (GEMM3 B)
//   [12M, 16M words)      : w_qkvT tf32 [3072][1024] (GEMM1 B)
//                           ... later reused for att tf32 [4096][1024]
// ---------------------------------------------------------------------------
#define OFF_QKV   0
#define OFF_WPROJ 0
#define OFF_U     (12u * 1024u * 1024u)
__device__ uint32_t g_heap[16u * 1024u * 1024u];

// ---------------------------------------------------------------------------
// helpers
// ---------------------------------------------------------------------------
__device__ __forceinline__ uint32_t f2tf(float x) {
    uint32_t u;
    asm("cvt.rna.tf32.f32 %0, %1;" : "=r"(u) : "f"(x));
    return u;
}
__device__ __forceinline__ uint32_t u2tf(uint32_t xb) {
    return f2tf(__uint_as_float(xb));
}
__device__ __forceinline__ uint32_t smaddr(const void* p) {
    return (uint32_t)__cvta_generic_to_shared(p);
}
__device__ __forceinline__ void ldmx4(uint32_t* r, uint32_t addr) {
    asm volatile("ldmatrix.sync.aligned.m8n8.x4.shared.b16 {%0,%1,%2,%3}, [%4];"
                 : "=r"(r[0]), "=r"(r[1]), "=r"(r[2]), "=r"(r[3]) : "r"(addr));
}
__device__ __forceinline__ void cpasync16(uint32_t dst, const void* src) {
    asm volatile("cp.async.cg.shared.global [%0], [%1], 16;" :: "r"(dst), "l"(src));
}
#define CP_COMMIT() asm volatile("cp.async.commit_group;")
#define CP_WAIT1()  asm volatile("cp.async.wait_group 1;")

// D(16x8) += A(16x8) * B(8x8); fp32 accum.
__device__ __forceinline__ void mma8(float* c, const uint32_t* a, const uint32_t* b) {
    asm volatile(
        "mma.sync.aligned.m16n8k8.row.col.f32.tf32.tf32.f32 "
        "{%0,%1,%2,%3}, {%4,%5,%6,%7}, {%8,%9}, {%0,%1,%2,%3};\n"
        : "+f"(c[0]), "+f"(c[1]), "+f"(c[2]), "+f"(c[3])
        : "r"(a[0]), "r"(a[1]), "r"(a[2]), "r"(a[3]), "r"(b[0]), "r"(b[1]));
}

// ---------------------------------------------------------------------------
// Transpose + convert: W [1024][Ncols] fp32 -> g_heap[dstOff..] [Ncols][1024] tf32
// ---------------------------------------------------------------------------
__global__ __launch_bounds__(256) void transpose_cvt(
    const float* __restrict__ W, unsigned dstOff, int Ncols)
{
    __shared__ uint32_t t[32][33];
    uint32_t* out = g_heap + dstOff;
    const int n0 = blockIdx.x * 32, k0 = blockIdx.y * 32;
    const int tx = threadIdx.x, ty = threadIdx.y;   // 32 x 8
#pragma unroll
    for (int i = 0; i < 32; i += 8)
        t[ty + i][tx] = f2tf(W[(size_t)(k0 + ty + i) * Ncols + n0 + tx]);
    __syncthreads();
#pragma unroll
    for (int i = 0; i < 32; i += 8)
        out[(size_t)(n0 + ty + i) * DMODEL + k0 + tx] = t[tx][ty + i];
}

// ---------------------------------------------------------------------------
// tf32 GEMM, double-buffered cp.async + ldmatrix.
// C[M=4096][N] = A[4096][1024] @ B^T (B stored [N][1024] n-major) + bias
// Block tile 128x128, BK=16, 256 thr = 8 warps (4m x 2n), warp 32x64.
//  MODE 0: A = x (fp32 param; cvt.rna in regs), B = heap+OFF_U (w_qkvT),
//          C = heap+OFF_QKV (tf32 bits)
//  MODE 1: A = heap+OFF_U (att tf32), B = heap+OFF_WPROJ (w_projT),
//          C = Cp (fp32)
// ---------------------------------------------------------------------------
#define TSTR 20                    // 16 + 4 pad words; ldmatrix rows hit all 32 banks
#define STAGE_BYTES (128 * TSTR * 4)

template<int MODE>
__global__ __launch_bounds__(256) void tgemm(
    const float* __restrict__ Ap, const float* __restrict__ bias,
    float* __restrict__ Cp, int N)
{
    const uint32_t* A = (MODE == 0) ? (const uint32_t*)Ap : g_heap + OFF_U;
    const uint32_t* B = (MODE == 0) ? g_heap + OFF_U : g_heap + OFF_WPROJ;
    uint32_t* Ctf = g_heap + OFF_QKV;
    constexpr int K = DMODEL;

    __shared__ uint32_t As[2][128][TSTR];
    __shared__ uint32_t Bs[2][128][TSTR];

    const int tid  = threadIdx.x;
    const int lane = tid & 31;
    const int wid  = tid >> 5;
    const int g    = lane >> 2;
    const int q    = lane & 3;

    const int bm = blockIdx.y * 128;
    const int bn = blockIdx.x * 128;
    const int wm0 = (wid >> 1) * 32;
    const int wn0 = (wid & 1) * 64;

    // cp.async mapping: thread -> one row, 32B (2 chunks) of each tile
    const int lrow = tid >> 1;
    const int lk   = (tid & 1) * 8;
    const uint32_t* Asrc = A + (size_t)(bm + lrow) * K + lk;
    const uint32_t* Bsrc = B + (size_t)(bn + lrow) * K + lk;
    const uint32_t dA = smaddr(&As[0][lrow][lk]);
    const uint32_t dB = smaddr(&Bs[0][lrow][lk]);

    // ldmatrix base addresses (stage 0); stage 1 = +STAGE_BYTES
    const int mat = lane >> 3, r = lane & 7;
    uint32_t aAddr[2], bAddr[4];
#pragma unroll
    for (int mt = 0; mt < 2; mt++)
        aAddr[mt] = smaddr(&As[0][wm0 + mt * 16 + (mat & 1) * 8 + r][(mat >> 1) * 4]);
#pragma unroll
    for (int jj = 0; jj < 4; jj++)
        bAddr[jj] = smaddr(&Bs[0][wn0 + jj * 16 + (mat >> 1) * 8 + r][(mat & 1) * 4]);

    float acc[2][8][4];
#pragma unroll
    for (int mt = 0; mt < 2; mt++)
#pragma unroll
        for (int j = 0; j < 8; j++)
#pragma unroll
            for (int v = 0; v < 4; v++) acc[mt][j][v] = 0.f;

    auto prefetch = [&](int kt, int s) {
        const uint32_t off = s * STAGE_BYTES;
        const uint32_t* a = Asrc + kt * 16;
        const uint32_t* b = Bsrc + kt * 16;
        cpasync16(dA + off, a);
        cpasync16(dA + off + 16, a + 4);
        cpasync16(dB + off, b);
        cpasync16(dB + off + 16, b + 4);
    };

    prefetch(0, 0);
    CP_COMMIT();

    const int NK = K / 16;   // 64
    for (int kt = 0; kt < NK; kt++) {
        const int s = kt & 1;
        if (kt + 1 < NK) prefetch(kt + 1, s ^ 1);
        CP_COMMIT();
        CP_WAIT1();
        __syncthreads();

        const uint32_t soff = s * STAGE_BYTES;
#pragma unroll
        for (int ks = 0; ks < 16; ks += 8) {
            uint32_t af[2][4];
            ldmx4(af[0], aAddr[0] + soff + ks * 4);
            ldmx4(af[1], aAddr[1] + soff + ks * 4);
            if (MODE == 0) {   // A holds raw fp32 bits of x: round to tf32 in regs
#pragma unroll
                for (int mt = 0; mt < 2; mt++)
#pragma unroll
                    for (int v = 0; v < 4; v++) af[mt][v] = u2tf(af[mt][v]);
            }
            uint32_t bf[4][4];
#pragma unroll
            for (int jj = 0; jj < 4; jj++)
                ldmx4(bf[jj], bAddr[jj] + soff + ks * 4);
#pragma unroll
            for (int mt = 0; mt < 2; mt++)
#pragma unroll
                for (int j = 0; j < 8; j++)
                    mma8(acc[mt][j], af[mt], &bf[j >> 1][(j & 1) * 2]);
        }
        __syncthreads();
    }

    // epilogue
#pragma unroll
    for (int mt = 0; mt < 2; mt++) {
        const int row0 = bm + wm0 + mt * 16 + g;
#pragma unroll
        for (int j = 0; j < 8; j++) {
            const int col = bn + wn0 + j * 8 + 2 * q;
            const float b0 = bias[col], b1 = bias[col + 1];
            if (MODE == 0) {
                *(uint2*)&Ctf[(size_t)row0 * N + col] =
                    make_uint2(f2tf(acc[mt][j][0] + b0), f2tf(acc[mt][j][1] + b1));
                *(uint2*)&Ctf[(size_t)(row0 + 8) * N + col] =
                    make_uint2(f2tf(acc[mt][j][2] + b0), f2tf(acc[mt][j][3] + b1));
            } else {
                *(float2*)&Cp[(size_t)row0 * N + col] =
                    make_float2(acc[mt][j][0] + b0, acc[mt][j][1] + b1);
                *(float2*)&Cp[(size_t)(row0 + 8) * N + col] =
                    make_float2(acc[mt][j][2] + b0, acc[mt][j][3] + b1);
            }
        }
    }
}

// ---------------------------------------------------------------------------
// Flash attention, tf32 tensor cores (qkv already tf32 bits).
// Grid: (16 q-tiles, 32 batch*head). Block: 256 threads = 8 warps.
// Reads qkv at heap+OFF_QKV, writes att at heap+OFF_U (over dead w_qkvT).
// ---------------------------------------------------------------------------
#define QSTR 68
#define KSTR 68
#define VSTR 72

#define SM_Q  0
#define SM_K  (SM_Q + 128 * QSTR)
#define SM_V  (SM_K + 64 * KSTR)
#define SM_P  (SM_V + 64 * VSTR)
#define SM_BIAS (SM_P + 128 * QSTR)
#define FLASH_SMEM_WORDS (SM_BIAS + 64)
#define FLASH_SMEM_BYTES (FLASH_SMEM_WORDS * 4)

__global__ __launch_bounds__(256) void flash_tf32(
    const float* __restrict__ attn_bias)   // [2][2048]
{
    const uint32_t* qkv = g_heap + OFF_QKV;
    uint32_t* att       = g_heap + OFF_U;

    extern __shared__ uint32_t smw[];
    uint32_t* Qs = smw + SM_Q;
    uint32_t* Ks = smw + SM_K;
    uint32_t* Vs = smw + SM_V;
    uint32_t* Ps = smw + SM_P;
    float* biass = (float*)(smw + SM_BIAS);

    const int tid  = threadIdx.x;
    const int lane = tid & 31;
    const int wid  = tid >> 5;
    const int g    = lane >> 2;
    const int q    = lane & 3;

    const int qtile = blockIdx.x;
    const int bh    = blockIdx.y;
    const int b = bh >> 4;
    const int h = bh & 15;
    const int q0 = qtile * 128;

    const int m = wid * 16 + g;

    // ---- load Q tile (already tf32) ----
    {
        const uint32_t* qbase = qkv + ((size_t)(b * SEQ + q0)) * 3072 + h * HDIM;
#pragma unroll
        for (int rep = 0; rep < 8; rep++) {
            int idx = rep * 256 + tid;
            int row = idx >> 4;
            int c4  = (idx & 15) * 4;
            *(uint4*)&Qs[row * QSTR + c4] = *(const uint4*)(qbase + (size_t)row * 3072 + c4);
        }
    }

    float o[8][4];
    float mr0 = -CUDART_INF_F, mr1 = -CUDART_INF_F;
    float l0 = 0.f, l1 = 0.f;
#pragma unroll
    for (int j = 0; j < 8; j++)
#pragma unroll
        for (int v = 0; v < 4; v++) o[j][v] = 0.f;

    for (int kt = 0; kt < SEQ / 64; kt++) {
        __syncthreads();
        {
            const uint32_t* kbase = qkv + ((size_t)(b * SEQ + kt * 64)) * 3072 + DMODEL + h * HDIM;
            const uint32_t* vbase = kbase + DMODEL;
#pragma unroll
            for (int rep = 0; rep < 4; rep++) {
                int idx = rep * 256 + tid;
                int key = idx >> 4;
                int c4  = (idx & 15) * 4;
                *(uint4*)&Ks[key * KSTR + c4] = *(const uint4*)(kbase + (size_t)key * 3072 + c4);
                *(uint4*)&Vs[key * VSTR + c4] = *(const uint4*)(vbase + (size_t)key * 3072 + c4);
            }
            if (tid < 16)
                *(float4*)&biass[tid * 4] =
                    *(const float4*)(attn_bias + (size_t)b * SEQ + kt * 64 + tid * 4);
        }
        __syncthreads();

        // ---- S = Q @ K^T ----
        float s[8][4];
#pragma unroll
        for (int j = 0; j < 8; j++)
#pragma unroll
            for (int v = 0; v < 4; v++) s[j][v] = 0.f;

#pragma unroll
        for (int ks = 0; ks < 64; ks += 8) {
            uint32_t af[4];
            af[0] = Qs[m * QSTR + ks + q];
            af[1] = Qs[(m + 8) * QSTR + ks + q];
            af[2] = Qs[m * QSTR + ks + q + 4];
            af[3] = Qs[(m + 8) * QSTR + ks + q + 4];
#pragma unroll
            for (int j = 0; j < 8; j++) {
                uint32_t bf[2];
                bf[0] = Ks[(j * 8 + g) * KSTR + ks + q];
                bf[1] = Ks[(j * 8 + g) * KSTR + ks + q + 4];
                mma8(s[j], af, bf);
            }
        }

        // ---- scale + bias, online softmax ----
        float mt0 = -CUDART_INF_F, mt1 = -CUDART_INF_F;
#pragma unroll
        for (int j = 0; j < 8; j++) {
            const int col = j * 8 + 2 * q;
            const float b0 = biass[col], b1 = biass[col + 1];
            s[j][0] = fmaf(s[j][0], 0.125f, b0);
            s[j][1] = fmaf(s[j][1], 0.125f, b1);
            s[j][2] = fmaf(s[j][2], 0.125f, b0);
            s[j][3] = fmaf(s[j][3], 0.125f, b1);
            mt0 = fmaxf(mt0, fmaxf(s[j][0], s[j][1]));
            mt1 = fmaxf(mt1, fmaxf(s[j][2], s[j][3]));
        }
        mt0 = fmaxf(mt0, __shfl_xor_sync(0xffffffffu, mt0, 1));
        mt0 = fmaxf(mt0, __shfl_xor_sync(0xffffffffu, mt0, 2));
        mt1 = fmaxf(mt1, __shfl_xor_sync(0xffffffffu, mt1, 1));
        mt1 = fmaxf(mt1, __shfl_xor_sync(0xffffffffu, mt1, 2));

        const float mn0 = fmaxf(mr0, mt0);
        const float mn1 = fmaxf(mr1, mt1);
        const float a0 = __expf(mr0 - mn0);
        const float a1 = __expf(mr1 - mn1);
        mr0 = mn0; mr1 = mn1;

        float rs0 = 0.f, rs1 = 0.f;
#pragma unroll
        for (int j = 0; j < 8; j++) {
            float p0 = __expf(s[j][0] - mn0);
            float p1 = __expf(s[j][1] - mn0);
            float p2 = __expf(s[j][2] - mn1);
            float p3 = __expf(s[j][3] - mn1);
            rs0 += p0 + p1;
            rs1 += p2 + p3;
            const int col = j * 8 + 2 * q;
            *(uint2*)&Ps[m * QSTR + col]       = make_uint2(f2tf(p0), f2tf(p1));
            *(uint2*)&Ps[(m + 8) * QSTR + col] = make_uint2(f2tf(p2), f2tf(p3));
        }
        rs0 += __shfl_xor_sync(0xffffffffu, rs0, 1);
        rs0 += __shfl_xor_sync(0xffffffffu, rs0, 2);
        rs1 += __shfl_xor_sync(0xffffffffu, rs1, 1);
        rs1 += __shfl_xor_sync(0xffffffffu, rs1, 2);
        l0 = l0 * a0 + rs0;
        l1 = l1 * a1 + rs1;

#pragma unroll
        for (int j = 0; j < 8; j++) {
            o[j][0] *= a0; o[j][1] *= a0;
            o[j][2] *= a1; o[j][3] *= a1;
        }
        __syncwarp();

        // ---- O += P @ V ----
#pragma unroll
        for (int ks = 0; ks < 64; ks += 8) {
            uint32_t af[4];
            af[0] = Ps[m * QSTR + ks + q];
            af[1] = Ps[(m + 8) * QSTR + ks + q];
            af[2] = Ps[m * QSTR + ks + q + 4];
            af[3] = Ps[(m + 8) * QSTR + ks + q + 4];
#pragma unroll
            for (int j = 0; j < 8; j++) {
                uint32_t bf[2];
                bf[0] = Vs[(ks + q) * VSTR + j * 8 + g];
                bf[1] = Vs[(ks + q + 4) * VSTR + j * 8 + g];
                mma8(o[j], af, bf);
            }
        }
        __syncwarp();
    }

    // ---- epilogue: normalize, store tf32 for proj GEMM ----
    const float inv0 = 1.0f / l0;
    const float inv1 = 1.0f / l1;
    const size_t row0 = (size_t)(b * SEQ + q0 + m);
#pragma unroll
    for (int j = 0; j < 8; j++) {
        const int col = h * HDIM + j * 8 + 2 * q;
        *(uint2*)&att[row0 * DMODEL + col] =
            make_uint2(f2tf(o[j][0] * inv0), f2tf(o[j][1] * inv0));
        *(uint2*)&att[(row0 + 8) * DMODEL + col] =
            make_uint2(f2tf(o[j][2] * inv1), f2tf(o[j][3] * inv1));
    }
}

// ---------------------------------------------------------------------------
// Launch (single stream; ordering provides the aliasing safety)
// ---------------------------------------------------------------------------
extern "C" void kernel_launch(void* const* d_in, const int* in_sizes, int n_in,
                              void* d_out, int out_size)
{
    const float* x      = (const float*)d_in[0];
    const float* attnb  = (const float*)d_in[1];
    const float* w_qkv  = (const float*)d_in[2];
    const float* b_qkv  = (const float*)d_in[3];
    const float* w_proj = (const float*)d_in[4];
    const float* b_proj = (const float*)d_in[5];
    float* out = (float*)d_out;

    cudaFuncSetAttribute(flash_tf32, cudaFuncAttributeMaxDynamicSharedMemorySize,
                         FLASH_SMEM_BYTES);

    // 1) w_qkv^T (tf32) -> heap+OFF_U
    transpose_cvt<<<dim3(3 * DMODEL / 32, DMODEL / 32), dim3(32, 8)>>>(w_qkv, OFF_U, 3 * DMODEL);

    // 2) qkv = x @ w_qkv + b_qkv -> heap+OFF_QKV (tf32)
    tgemm<0><<<dim3(3 * DMODEL / 128, MROWS / 128), 256>>>(x, b_qkv, nullptr, 3 * DMODEL);

    // 3) attention: qkv -> att at heap+OFF_U (w_qkvT now dead)
    flash_tf32<<<dim3(SEQ / 128, BATCH * NHEAD), 256, FLASH_SMEM_BYTES>>>(attnb);

    // 4) w_proj^T (tf32) -> heap+OFF_WPROJ (qkv now dead)
    transpose_cvt<<<dim3(DMODEL / 32, DMODEL / 32), dim3(32, 8)>>>(w_proj, OFF_WPROJ, DMODEL);

    // 5) out = att @ w_proj + b_proj (fp32)
    tgemm<1><<<dim3(DMODEL / 128, MROWS / 128), 256>>>(nullptr, b_proj, out, DMODEL);
}